// round 15
// baseline (speedup 1.0000x reference)
#include <cuda_runtime.h>
#include <math.h>

#define NB    32
#define NF    500
#define FEAT  256
#define COUT  2
#define CIN   2
#define KK    16
#define FRAME 160
#define OVL   40
#define NSAMP (NF * FRAME)          // 80000
#define NFILT (COUT * CIN * KK)     // 64

#define GAIN_A 0.69077552789821368f
#define SG     0.50118723362727224f
#define OMSG   0.49881276637272776f

// Per-frame filters: [(b*NF+f)*64 + cout*32 + cin*16 + k]
__device__ float g_w[(size_t)NB * NF * NFILT];
// Per-filt-block done flags (zeroed each launch by zflag_kernel)
__device__ unsigned g_done[512];

__global__ void zflag_kernel() {
    int i = blockIdx.x * 256 + threadIdx.x;
    if (i < 512) g_done[i] = 0u;
}

// ===========================================================================
// Fused kernel: blocks 0..499 = filt role (32 feature-rows each);
// blocks 500..4499 = conv role (R12 formulation), spinning on the <=2
// filt-block flags covering the 5 filter rows they need.
// 128 threads, lb(128,8) -> >=1184 wave-1 blocks >> 500 filt blocks
// (deadlock-free: filt blocks are first in bid order).
// ===========================================================================
#define NFB    500
#define FBROWS 32
#define FPB    4
#define XROW   176
#define NCONV  (NB * (NF / FPB))    // 4000

__global__ void __launch_bounds__(128, 8) fused_kernel(
    const float* __restrict__ feat,
    const float* __restrict__ ckw,
    const float* __restrict__ ckb,
    const float* __restrict__ fgw,
    const float* __restrict__ fgb,
    const float* __restrict__ x,
    const float* __restrict__ owin,
    float* __restrict__ out)
{
    __shared__ __align__(16) float smu[3108];   // union: conv 3108f / filt 2368f
    int tid = threadIdx.x;
    int bid = blockIdx.x;

    if (bid < NFB) {
        // ================= filt role =================
        float*  Wt   = smu;                      // [32 fe-chunk][68] (raw aliases)
        float*  gg   = smu + 2176;               // [64]
        float*  invn = gg + 64;
        float*  gain = invn + 64;
        float4* Wt4  = (float4*)Wt;

        int bf0  = bid * FBROWS;                 // global feature-row base
        int ogrp = tid & 15, rgrp = tid >> 4;
        int o0 = ogrp * 4, r0 = rgrp * 4;

        const float4* feat4 = (const float4*)feat;
        const float4* ckw4  = (const float4*)ckw;

        float acc[4][4];
        #pragma unroll
        for (int i = 0; i < 4; ++i)
            #pragma unroll
            for (int j = 0; j < 4; ++j) acc[i][j] = 0.f;

        for (int c = 0; c < 8; ++c) {            // 8 chunks of 32 fe
            __syncthreads();                     // prior chunk's LDS done
            #pragma unroll
            for (int k2 = 0; k2 < 4; ++k2) {     // stage Wt chunk (512 float4)
                int idx = tid + 128 * k2;
                int o = idx >> 3, f4l = idx & 7;
                float4 v = __ldg(&ckw4[(size_t)o * 64 + c * 8 + f4l]);
                Wt[(4 * f4l + 0) * 68 + o] = v.x;
                Wt[(4 * f4l + 1) * 68 + o] = v.y;
                Wt[(4 * f4l + 2) * 68 + o] = v.z;
                Wt[(4 * f4l + 3) * 68 + o] = v.w;
            }
            __syncthreads();
            #pragma unroll 2
            for (int f4 = 0; f4 < 8; ++f4) {
                float4 fv[4];
                #pragma unroll
                for (int i = 0; i < 4; ++i)
                    fv[i] = __ldg(&feat4[(size_t)(bf0 + r0 + i) * 64 + c * 8 + f4]);
                float4 w0 = Wt4[(4 * f4 + 0) * 17 + ogrp];
                float4 w1 = Wt4[(4 * f4 + 1) * 17 + ogrp];
                float4 w2 = Wt4[(4 * f4 + 2) * 17 + ogrp];
                float4 w3 = Wt4[(4 * f4 + 3) * 17 + ogrp];
                #pragma unroll
                for (int i = 0; i < 4; ++i) {
                    acc[i][0] = fmaf(fv[i].x, w0.x, acc[i][0]);
                    acc[i][1] = fmaf(fv[i].x, w0.y, acc[i][1]);
                    acc[i][2] = fmaf(fv[i].x, w0.z, acc[i][2]);
                    acc[i][3] = fmaf(fv[i].x, w0.w, acc[i][3]);
                    acc[i][0] = fmaf(fv[i].y, w1.x, acc[i][0]);
                    acc[i][1] = fmaf(fv[i].y, w1.y, acc[i][1]);
                    acc[i][2] = fmaf(fv[i].y, w1.z, acc[i][2]);
                    acc[i][3] = fmaf(fv[i].y, w1.w, acc[i][3]);
                    acc[i][0] = fmaf(fv[i].z, w2.x, acc[i][0]);
                    acc[i][1] = fmaf(fv[i].z, w2.y, acc[i][1]);
                    acc[i][2] = fmaf(fv[i].z, w2.z, acc[i][2]);
                    acc[i][3] = fmaf(fv[i].z, w2.w, acc[i][3]);
                    acc[i][0] = fmaf(fv[i].w, w3.x, acc[i][0]);
                    acc[i][1] = fmaf(fv[i].w, w3.y, acc[i][1]);
                    acc[i][2] = fmaf(fv[i].w, w3.z, acc[i][2]);
                    acc[i][3] = fmaf(fv[i].w, w3.w, acc[i][3]);
                }
            }
        }

        // gain logits (global feat + fgw, L2-hot)
        if (tid < FBROWS * 2) {
            int r = tid >> 1, cc = tid & 1;
            const float4* fr = feat4 + (size_t)(bf0 + r) * 64;
            const float4* gw = (const float4*)fgw + cc * 64;
            float s = 0.f;
            #pragma unroll 4
            for (int q = 0; q < 64; ++q) {
                float4 a = __ldg(&fr[q]);
                float4 b = __ldg(&gw[q]);
                s += a.x * b.x + a.y * b.y + a.z * b.z + a.w * b.w;
            }
            gg[tid] = s + __ldg(&fgb[cc]);
        }
        __syncthreads();                         // Wt LDS done -> raw may alias
        float* raw = Wt;
        #pragma unroll
        for (int i = 0; i < 4; ++i)
            #pragma unroll
            for (int j = 0; j < 4; ++j)
                raw[(r0 + i) * 68 + (o0 + j)] = acc[i][j] + __ldg(&ckb[o0 + j]);
        __syncthreads();

        if (tid < FBROWS * 2) {
            int r = tid >> 1, cc = tid & 1;
            float ss = 0.f;
            #pragma unroll
            for (int i = 0; i < 32; ++i) {
                float v = raw[r * 68 + cc * 32 + i];
                ss += v * v;
            }
            invn[tid] = 1.0f / (1e-6f + sqrtf(ss));
            gain[tid] = expf(GAIN_A * tanhf(gg[tid]));
        }
        __syncthreads();

        for (int idx = tid; idx < FBROWS * NFILT; idx += 128) {
            int r = idx >> 6, o = idx & 63;
            int co = o >> 5;
            float v = SG * raw[r * 68 + o] * invn[r * 2 + co];
            if ((o & 15) == 7) v += OMSG;        // identity tap k=7
            g_w[(size_t)(bf0 + r) * NFILT + o] = v * gain[r * 2 + co];
        }
        __threadfence();
        __syncthreads();
        if (tid == 0) atomicExch(&g_done[bid], 1u);

    } else {
        // ================= conv role (R12) =================
        float (*xs)[FPB * XROW]      = (float(*)[FPB * XROW])smu;   // [2][704]
        float* wsm                   = smu + 1408;                  // [340]
        float (*ob)[COUT][FRAME]     = (float(*)[COUT][FRAME])(smu + 1748);
        float* w1s                   = smu + 1748 + FPB * COUT * FRAME; // [40]
        float* w2s                   = w1s + OVL;                       // [40]

        const int NT = 128;
        int cb = bid - NFB;
        int b  = cb / (NF / FPB);
        int f0 = (cb % (NF / FPB)) * FPB;
        int lane = tid & 31;
        int w    = tid >> 5;

        const float* xb = x + (size_t)b * CIN * NSAMP;
        for (int i = tid; i < CIN * FPB * 44; i += NT) {
            int ci  = i / (FPB * 44);
            int rem = i - ci * (FPB * 44);
            int f   = rem / 44, q = rem - f * 44;
            int gb  = (f0 + f) * FRAME - 16 + q * 4;
            float4 v = make_float4(0.f, 0.f, 0.f, 0.f);
            if (gb >= 0)
                v = *(const float4*)(xb + (size_t)ci * NSAMP + gb);
            *(float4*)&xs[ci][f * XROW + q * 4] = v;
        }
        if (tid < OVL) {
            w2s[tid] = owin[tid];
            w1s[tid] = owin[OVL - 1 - tid];
        }

        // ---- wait for the filter rows this block needs ----
        if (tid == 0) {
            int rlo = b * NF + ((f0 > 0) ? f0 - 1 : 0);
            int rhi = b * NF + f0 + FPB - 1;
            int b0 = rlo >> 5, b1 = rhi >> 5;
            while (atomicAdd(&g_done[b0], 0u) == 0u) __nanosleep(128);
            if (b1 != b0)
                while (atomicAdd(&g_done[b1], 0u) == 0u) __nanosleep(128);
        }
        __syncthreads();

        for (int i = tid; i < (FPB + 1) * 64; i += NT) {
            int fr = i >> 6, o = i & 63;
            int fi = f0 - 1 + fr;
            wsm[fr * 68 + o] = (fi >= 0)
                ? g_w[((size_t)b * NF + fi) * NFILT + o] : 0.f;
        }
        __syncthreads();

        int p   = w >> 1, jh = w & 1;
        int l16 = lane & 15, fsel = lane >> 4;
        int fl  = 2 * p + fsel;
        int j0  = jh * 80 + 5 * l16;
        int xbase = fl * XROW + 1 + j0;

        float a0[5] = {0,0,0,0,0}, a1[5] = {0,0,0,0,0};
        float p0[5] = {0,0,0,0,0}, p1[5] = {0,0,0,0,0};

        const float4* wc = (const float4*)(wsm + (fl + 1) * 68);
        const float4* wp = (const float4*)(wsm + fl * 68);
        bool tail = (j0 < OVL);

        #pragma unroll
        for (int ci = 0; ci < CIN; ++ci) {
            float xw[20];
            #pragma unroll
            for (int i = 0; i < 20; ++i)
                xw[i] = xs[ci][xbase + i];

            #pragma unroll
            for (int kc = 0; kc < 4; ++kc) {
                float4 c0 = wc[ci * 4 + kc];
                float4 c1 = wc[8 + ci * 4 + kc];
                float wk0[4] = {c0.x, c0.y, c0.z, c0.w};
                float wk1[4] = {c1.x, c1.y, c1.z, c1.w};
                #pragma unroll
                for (int kk = 0; kk < 4; ++kk) {
                    int k = 4 * kc + kk;
                    #pragma unroll
                    for (int m = 0; m < 5; ++m) {
                        float xv = xw[m + 15 - k];
                        a0[m] = fmaf(wk0[kk], xv, a0[m]);
                        a1[m] = fmaf(wk1[kk], xv, a1[m]);
                    }
                }
            }
            if (tail) {
                #pragma unroll
                for (int kc = 0; kc < 4; ++kc) {
                    float4 c0 = wp[ci * 4 + kc];
                    float4 c1 = wp[8 + ci * 4 + kc];
                    float wk0[4] = {c0.x, c0.y, c0.z, c0.w};
                    float wk1[4] = {c1.x, c1.y, c1.z, c1.w};
                    #pragma unroll
                    for (int kk = 0; kk < 4; ++kk) {
                        int k = 4 * kc + kk;
                        #pragma unroll
                        for (int m = 0; m < 5; ++m) {
                            float xv = xw[m + 15 - k];
                            p0[m] = fmaf(wk0[kk], xv, p0[m]);
                            p1[m] = fmaf(wk1[kk], xv, p1[m]);
                        }
                    }
                }
            }
        }

        if (tail) {
            #pragma unroll
            for (int m = 0; m < 5; ++m) {
                int j = j0 + m;
                ob[fl][0][j] = w1s[j] * a0[m] + w2s[j] * p0[m];
                ob[fl][1][j] = w1s[j] * a1[m] + w2s[j] * p1[m];
            }
        } else {
            #pragma unroll
            for (int m = 0; m < 5; ++m) {
                int j = j0 + m;
                ob[fl][0][j] = a0[m];
                ob[fl][1][j] = a1[m];
            }
        }
        __syncthreads();

        int f = f0 + w;
        #pragma unroll
        for (int co = 0; co < COUT; ++co) {
            float4* op = (float4*)(out + (size_t)b * COUT * NSAMP
                                   + (size_t)co * NSAMP + (size_t)f * FRAME);
            const float4* obp = (const float4*)ob[w][co];
            #pragma unroll
            for (int i = lane; i < FRAME / 4; i += 32)
                op[i] = obp[i];
        }
    }
}

extern "C" void kernel_launch(void* const* d_in, const int* in_sizes, int n_in,
                              void* d_out, int out_size)
{
    const float* x    = (const float*)d_in[0];
    const float* feat = (const float*)d_in[1];
    const float* ckw  = (const float*)d_in[2];
    const float* ckb  = (const float*)d_in[3];
    const float* fgw  = (const float*)d_in[4];
    const float* fgb  = (const float*)d_in[5];
    const float* ow   = (const float*)d_in[6];
    float* out = (float*)d_out;

    zflag_kernel<<<2, 256>>>();
    fused_kernel<<<NFB + NCONV, 128>>>(feat, ckw, ckb, fgw, fgb, x, ow, out);
}